// round 2
// baseline (speedup 1.0000x reference)
#include <cuda_runtime.h>
#include <math.h>

#define FS    39      // total fields
#define NF    38      // fields in pairwise term (0..37)
#define NP    703     // NF*(NF-1)/2
#define FEAT  100000
#define EMB   10
#define BATCH 2048
#define TPB   256
#define CHUNKS 4              // batch chunks per pair
#define CB    (BATCH/CHUNKS)  // 512 batches per CTA
#define ITEMS (CB/TPB)        // 2 items per thread

// Scratch (allocation-free): transposed idx/vals + per-batch accumulator.
__device__ int   g_idxT[FS * BATCH];
__device__ float g_valT[FS * BATCH];
__device__ float g_acc[BATCH];

// Kernel 0: transpose idxs/vals into field-major layout, zero accumulator.
__global__ void ffm_prep(const int* __restrict__ idxs,
                         const float* __restrict__ vals)
{
    int tid = blockIdx.x * blockDim.x + threadIdx.x;
    if (tid < FS * BATCH) {
        int f = tid / BATCH;
        int b = tid - f * BATCH;
        g_idxT[tid] = idxs[b * FS + f];
        g_valT[tid] = vals[b * FS + f];
    }
    if (tid < BATCH) g_acc[tid] = 0.f;
}

// Kernel 1: pair-major gather + dot. blockIdx.y = pair, blockIdx.x = batch chunk.
// All CTAs of a pair run adjacently -> each table's touched lines stay hot in L2.
__global__ __launch_bounds__(TPB) void ffm_pairs(const float* __restrict__ emb)
{
    // Decode pair index -> (i, j), uniform across the CTA (cheap ALU loop).
    int p = blockIdx.y;
    int i = 0, rem = p;
    while (rem >= NF - 1 - i) { rem -= NF - 1 - i; ++i; }
    const int j = i + 1 + rem;

    const int* __restrict__ idxI = g_idxT + i * BATCH;
    const int* __restrict__ idxJ = g_idxT + j * BATCH;
    const float* __restrict__ valI = g_valT + i * BATCH;
    const float* __restrict__ valJ = g_valT + j * BATCH;

    int b = blockIdx.x * CB + threadIdx.x;

    #pragma unroll
    for (int s = 0; s < ITEMS; ++s, b += TPB) {
        const int   xi = idxI[b];
        const int   xj = idxJ[b];
        const float vi = valI[b];
        const float vj = valJ[b];

        const float2* __restrict__ A =
            (const float2*)(emb + ((size_t)i * FEAT + xj) * EMB);
        const float2* __restrict__ B =
            (const float2*)(emb + ((size_t)j * FEAT + xi) * EMB);
        float2 a0 = A[0], a1 = A[1], a2 = A[2], a3 = A[3], a4 = A[4];
        float2 b0 = B[0], b1 = B[1], b2 = B[2], b3 = B[3], b4 = B[4];
        float dot = a0.x * b0.x + a0.y * b0.y
                  + a1.x * b1.x + a1.y * b1.y
                  + a2.x * b2.x + a2.y * b2.y
                  + a3.x * b3.x + a3.y * b3.y
                  + a4.x * b4.x + a4.y * b4.y;

        atomicAdd(&g_acc[b], dot * vi * vj);
    }
}

// Kernel 2: first-order term + sigmoid.
__global__ void ffm_finalize(const float* __restrict__ w1,
                             float* __restrict__ out)
{
    int b = blockIdx.x * blockDim.x + threadIdx.x;
    if (b >= BATCH) return;
    float first = 0.f;
    #pragma unroll
    for (int f = 0; f < FS; ++f) {
        first += w1[g_idxT[f * BATCH + b]] * g_valT[f * BATCH + b];
    }
    float tot = first + g_acc[b];
    out[b] = 1.f / (1.f + expf(-tot));
}

extern "C" void kernel_launch(void* const* d_in, const int* in_sizes, int n_in,
                              void* d_out, int out_size) {
    const int*   idxs = (const int*)d_in[0];
    const float* vals = (const float*)d_in[1];
    const float* emb  = (const float*)d_in[2];
    const float* w1   = (const float*)d_in[3];
    float* out = (float*)d_out;

    ffm_prep<<<(FS * BATCH + TPB - 1) / TPB, TPB>>>(idxs, vals);

    dim3 grid(CHUNKS, NP);
    ffm_pairs<<<grid, TPB>>>(emb);

    ffm_finalize<<<(BATCH + TPB - 1) / TPB, TPB>>>(w1, out);
}

// round 4
// speedup vs baseline: 1.1000x; 1.1000x over previous
#include <cuda_runtime.h>
#include <math.h>

#define FS   39      // total fields
#define NF   38      // fields in pairwise term (0..37)
#define NP   703     // NF*(NF-1)/2 pairs
#define FEAT 100000
#define EMB  10
#define TPB  256
#define NQUAD (TPB / 4)   // 64 quads per CTA

__global__ __launch_bounds__(TPB) void ffm_kernel(
    const int*   __restrict__ idxs,   // [B, FS]
    const float* __restrict__ vals,   // [B, FS]
    const float* __restrict__ emb,    // [FS, FEAT, EMB]
    const float* __restrict__ w1,     // [FEAT]
    float*       __restrict__ out)    // [B]
{
    __shared__ int   s_idx[FS];
    __shared__ float s_val[FS];
    __shared__ unsigned char s_i[NP];
    __shared__ unsigned char s_j[NP];
    __shared__ float s_red[TPB / 32];

    const int b = blockIdx.x;
    const int t = threadIdx.x;

    if (t < FS) {
        s_idx[t] = idxs[b * FS + t];
        s_val[t] = vals[b * FS + t];
    }
    // Cooperative pair-table fill: thread i owns row i of the upper triangle.
    if (t < NF - 1) {
        const int i = t;
        const int base = i * (2 * NF - i - 1) / 2;
        #pragma unroll 1
        for (int j = i + 1; j < NF; j++) {
            s_i[base + j - i - 1] = (unsigned char)i;
            s_j[base + j - i - 1] = (unsigned char)j;
        }
    }
    __syncthreads();

    float acc = 0.f;

    // First-order term folded into the reduction.
    if (t < FS) {
        acc = w1[s_idx[t]] * s_val[t];
    }

    // Second-order: one 4-lane quad per pair. Lane l loads float2 chunk l of
    // both 40B rows (warp-wide LDG.64 covers 8 rows x 32B contiguous -> far
    // fewer L1 wavefronts than per-thread scattered loads); lane 0 adds the
    // 8B tails. Each lane scales its OWN partial by v_i*v_j and accumulates
    // privately -- no intra-quad shuffle, so divergent trip counts are safe.
    // The block reduction at the end sums everything.
    const int quad = t >> 2;   // 0..63
    const int lane = t & 3;

    #pragma unroll 2
    for (int p = quad; p < NP; p += NQUAD) {
        const int i = s_i[p];
        const int j = s_j[p];
        const float2* __restrict__ A =
            (const float2*)(emb + ((size_t)i * FEAT + s_idx[j]) * EMB);
        const float2* __restrict__ B =
            (const float2*)(emb + ((size_t)j * FEAT + s_idx[i]) * EMB);

        const float2 a = A[lane];
        const float2 v = B[lane];
        float partial = a.x * v.x + a.y * v.y;
        if (lane == 0) {
            const float2 at = A[4];
            const float2 vt = B[4];
            partial += at.x * vt.x + at.y * vt.y;
        }
        acc += partial * s_val[i] * s_val[j];
    }

    // Block reduction (all 256 threads reach here converged).
    #pragma unroll
    for (int o = 16; o > 0; o >>= 1)
        acc += __shfl_down_sync(0xffffffffu, acc, o);
    if ((t & 31) == 0) s_red[t >> 5] = acc;
    __syncthreads();
    if (t == 0) {
        float tot = 0.f;
        #pragma unroll
        for (int w = 0; w < TPB / 32; w++) tot += s_red[w];
        out[b] = 1.f / (1.f + expf(-tot));
    }
}

extern "C" void kernel_launch(void* const* d_in, const int* in_sizes, int n_in,
                              void* d_out, int out_size) {
    const int*   idxs = (const int*)d_in[0];
    const float* vals = (const float*)d_in[1];
    const float* emb  = (const float*)d_in[2];
    const float* w1   = (const float*)d_in[3];
    float* out = (float*)d_out;

    const int batch = out_size;  // 2048
    ffm_kernel<<<batch, TPB>>>(idxs, vals, emb, w1, out);
}

// round 5
// speedup vs baseline: 1.1968x; 1.0880x over previous
#include <cuda_runtime.h>
#include <math.h>

#define FS    39      // total fields
#define NF    38      // fields in pairwise term (0..37)
#define NP    703     // NF*(NF-1)/2 pairs
#define NITEM (NP*5)  // 3515 work items: (pair, float2-chunk)
#define FEAT  100000
#define EMB   10
#define TPB   256
#define KMAX  ((NITEM + TPB - 1) / TPB)   // 14

__global__ __launch_bounds__(TPB) void ffm_kernel(
    const int*   __restrict__ idxs,   // [B, FS]
    const float* __restrict__ vals,   // [B, FS]
    const float* __restrict__ emb,    // [FS, FEAT, EMB]
    const float* __restrict__ w1,     // [FEAT]
    float*       __restrict__ out)    // [B]
{
    __shared__ int   s_idx[FS];
    __shared__ float s_val[FS];
    __shared__ int4  s_pair[NP];      // {offA, offB, bits(v_i*v_j), pad}
    __shared__ float s_red[TPB / 32];

    const int b = blockIdx.x;
    const int t = threadIdx.x;

    if (t < FS) {
        s_idx[t] = idxs[b * FS + t];
        s_val[t] = vals[b * FS + t];
    }
    __syncthreads();

    // Prologue: precompute per-pair descriptors so the main loop has zero
    // dependent address math. ~3 pairs per thread.
    for (int p = t; p < NP; p += TPB) {
        // decode triangular index p -> (i, j), i < j <= NF-1
        int i = 0, rem = p;
        while (rem >= NF - 1 - i) { rem -= NF - 1 - i; ++i; }
        const int j = i + 1 + rem;
        int4 d;
        d.x = (i * FEAT + s_idx[j]) * EMB;   // row A: emb[i][idx_j]
        d.y = (j * FEAT + s_idx[i]) * EMB;   // row B: emb[j][idx_i]
        d.z = __float_as_int(s_val[i] * s_val[j]);
        d.w = 0;
        s_pair[p] = d;
    }

    float acc = 0.f;
    if (t < FS) {
        acc = w1[s_idx[t]] * s_val[t];       // first-order term
    }
    __syncthreads();

    // Main loop: perfectly balanced flat items. item = p*5 + c.
    // Per item: 1 LDS.128 (descriptor) + 2 LDG.64 + 3 FFMA.
    // Consecutive lanes take consecutive chunks -> warp-wide LDGs cover
    // whole 40B rows contiguously.
    #pragma unroll
    for (int k = 0; k < KMAX; ++k) {
        const int item = t + k * TPB;
        if (item < NITEM) {
            const int p = item / 5;
            const int c = item - p * 5;
            const int4 d = s_pair[p];
            const float2 a = *(const float2*)(emb + d.x + 2 * c);
            const float2 v = *(const float2*)(emb + d.y + 2 * c);
            acc += __int_as_float(d.z) * (a.x * v.x + a.y * v.y);
        }
    }

    // Block reduction.
    #pragma unroll
    for (int o = 16; o > 0; o >>= 1)
        acc += __shfl_down_sync(0xffffffffu, acc, o);
    if ((t & 31) == 0) s_red[t >> 5] = acc;
    __syncthreads();
    if (t == 0) {
        float tot = 0.f;
        #pragma unroll
        for (int w = 0; w < TPB / 32; w++) tot += s_red[w];
        out[b] = 1.f / (1.f + expf(-tot));
    }
}

extern "C" void kernel_launch(void* const* d_in, const int* in_sizes, int n_in,
                              void* d_out, int out_size) {
    const int*   idxs = (const int*)d_in[0];
    const float* vals = (const float*)d_in[1];
    const float* emb  = (const float*)d_in[2];
    const float* w1   = (const float*)d_in[3];
    float* out = (float*)d_out;

    const int batch = out_size;  // 2048
    ffm_kernel<<<batch, TPB>>>(idxs, vals, emb, w1, out);
}

// round 6
// speedup vs baseline: 1.2359x; 1.0327x over previous
#include <cuda_runtime.h>
#include <math.h>

#define FS    39      // total fields
#define NF    38      // fields in pairwise term (0..37)
#define NP    703     // NF*(NF-1)/2 pairs
#define NITEM (NP*5)  // 3515 work items: (pair, float2-chunk)
#define FEAT  100000
#define EMB   10
#define ROWB  (EMB*4) // 40 bytes per embedding row
#define TPB   256
#define KMAX  14      // ceil(NITEM / TPB)
#define NPPAD 720     // padded pair table (max p touched = 716)

__global__ __launch_bounds__(TPB) void ffm_kernel(
    const int*   __restrict__ idxs,   // [B, FS]
    const float* __restrict__ vals,   // [B, FS]
    const float* __restrict__ emb,    // [FS, FEAT, EMB]
    const float* __restrict__ w1,     // [FEAT]
    float*       __restrict__ out)    // [B]
{
    __shared__ int   s_idx[FS];
    __shared__ float s_val[FS];
    __shared__ int4  s_pair[NPPAD];   // {byteOffA, byteOffB, bits(v_i*v_j), pad}
    __shared__ float s_red[TPB / 32];

    const int b = blockIdx.x;
    const int t = threadIdx.x;

    if (t < FS) {
        s_idx[t] = idxs[b * FS + t];
        s_val[t] = vals[b * FS + t];
    }
    __syncthreads();

    // Zero-scale padding so the main loop needs no bounds guard.
    for (int p = NP + t; p < NPPAD; p += TPB) {
        s_pair[p] = make_int4(0, 0, 0, 0);
    }

    // Prologue: closed-form triangular decode p -> (i, j), then byte-offset
    // descriptors. base(i) = i*(75-i)/2 for NF=38.
    for (int p = t; p < NP; p += TPB) {
        int i = (int)((75.0f - sqrtf(5625.0f - 8.0f * (float)p)) * 0.5f);
        if (p < i * (75 - i) / 2) --i;                       // float rounding fixups
        else if (p >= (i + 1) * (74 - i) / 2) ++i;
        const int base = i * (75 - i) / 2;
        const int j = p - base + i + 1;
        int4 d;
        d.x = (i * FEAT + s_idx[j]) * ROWB;   // row A byte offset: emb[i][idx_j]
        d.y = (j * FEAT + s_idx[i]) * ROWB;   // row B byte offset: emb[j][idx_i]
        d.z = __float_as_int(s_val[i] * s_val[j]);
        d.w = 0;
        s_pair[p] = d;
    }

    float acc = 0.f, acc2 = 0.f;
    if (t < FS) {
        acc = w1[s_idx[t]] * s_val[t];        // first-order term
    }
    __syncthreads();

    // Main loop: uniform 14 items/thread. Per item: 1 LDS.128 + 2 LDG.64 +
    // 3 FFMA + incremental (p, chunk-byte) update (stride 256 = 51*5 + 1).
    // No division, no guard, no dependent address math.
    const char* __restrict__ embB = (const char*)emb;
    int p  = t / 5;               // once (magic multiply)
    int cb = (t - p * 5) * 8;     // chunk byte offset within the 40B row

    #pragma unroll
    for (int k = 0; k < KMAX; ++k) {
        const int4 d = s_pair[p];
        const float2 a = *(const float2*)(embB + (unsigned)(d.x + cb));
        const float2 v = *(const float2*)(embB + (unsigned)(d.y + cb));
        const float s = __int_as_float(d.z);
        if (k & 1) acc2 += s * (a.x * v.x + a.y * v.y);
        else       acc  += s * (a.x * v.x + a.y * v.y);
        p += 51; cb += 8;
        if (cb >= ROWB) { cb -= ROWB; ++p; }
    }
    acc += acc2;

    // Block reduction.
    #pragma unroll
    for (int o = 16; o > 0; o >>= 1)
        acc += __shfl_down_sync(0xffffffffu, acc, o);
    if ((t & 31) == 0) s_red[t >> 5] = acc;
    __syncthreads();
    if (t == 0) {
        float tot = 0.f;
        #pragma unroll
        for (int w = 0; w < TPB / 32; w++) tot += s_red[w];
        out[b] = 1.f / (1.f + expf(-tot));
    }
}

extern "C" void kernel_launch(void* const* d_in, const int* in_sizes, int n_in,
                              void* d_out, int out_size) {
    const int*   idxs = (const int*)d_in[0];
    const float* vals = (const float*)d_in[1];
    const float* emb  = (const float*)d_in[2];
    const float* w1   = (const float*)d_in[3];
    float* out = (float*)d_out;

    const int batch = out_size;  // 2048
    ffm_kernel<<<batch, TPB>>>(idxs, vals, emb, w1, out);
}